// round 5
// baseline (speedup 1.0000x reference)
#include <cuda_runtime.h>
#include <cuda_bf16.h>

// Circular self-convolution: out[b,k] = sum_j x[b,j]*x[b,(k-j) mod 1024]
// B=128 rows x 3 arrays. One CTA (512 threads) per (array,row).
//
// FFMA2 (fma.rn.f32x2) j-paired tile from R4 (zero operand marshaling),
// unchanged per-warp. NEW: 4-way j-split inside the CTA to fix the R4
// latency collapse (occ 13%, issue 36%):
//   warps with jh = tid>>7 accumulate j in [256*jh, 256*jh+256)
//   -> 16 warps/CTA, ~41 warps/SM, identical FFMA2:LDS ratio.
// Partial sums combined via a small smem reduction.
//
// Tile recap: each thread -> 8 outputs strided by 2 (parity split, RE/RO
// reversed copies offset one float). FFMA2 lanes = two adjacent j-terms of
// one output: (x[j],x[j+1]) * (x[k-j],x[k-j-1]); the reversed smem copies
// make both operands natural aligned u64 halves of LDS.128. Reversed arrays
// padded 16->20 floats/block => conflict-free lane stride (80B).

#define N_CONV 1024
#define THREADS 512
#define JH_SPLIT 4
#define ITERS (N_CONV / 16 / JH_SPLIT)   // 16

typedef unsigned long long u64t;

__device__ __forceinline__ u64t ffma2(u64t a, u64t b, u64t c) {
    u64t d;
    asm("fma.rn.f32x2 %0, %1, %2, %3;" : "=l"(d) : "l"(a), "l"(b), "l"(c));
    return d;
}
__device__ __forceinline__ void unpack2(u64t v, float& lo, float& hi) {
    asm("mov.b64 {%0, %1}, %2;" : "=f"(lo), "=f"(hi) : "l"(v));
}

// Padded layout: 16 logical floats per 20-float physical block.
__device__ __forceinline__ int padidx(int u) { return (u >> 4) * 20 + (u & 15); }

// Load 4 float4 (16 floats) as 8 u64 pairs.
__device__ __forceinline__ void load8u64(u64t* w, const float* p) {
    const ulonglong2* q = (const ulonglong2*)p;
    #pragma unroll
    for (int i = 0; i < 4; ++i) {
        ulonglong2 v = q[i];
        w[2 * i]     = v.x;
        w[2 * i + 1] = v.y;
    }
}

__global__ __launch_bounds__(THREADS, 2)
void mcf_conv_kernel(const float* __restrict__ x1,
                     const float* __restrict__ x2,
                     const float* __restrict__ x3,
                     float* __restrict__ out)
{
    // RE[u] = x[(1022-u) mod 1024], RO[u] = x[(1023-u) mod 1024]; u in [0,2064)
    // padded: 129 blocks * 20 floats = 2580.
    __shared__ __align__(16) float RE[2580];
    __shared__ __align__(16) float RO[2580];
    __shared__ __align__(16) float X[N_CONV];
    __shared__ __align__(16) float SP[3 * N_CONV];   // partials from jh=1..3

    const int bx  = blockIdx.x;
    const int arr = bx >> 7;
    const int row = bx & 127;

    const float* x  = (arr == 0) ? x1 : ((arr == 1) ? x2 : x3);
    const float* xr = x + (size_t)row * N_CONV;

    const int tid = threadIdx.x;

    for (int u = tid; u < 2064; u += THREADS) {
        const int p = padidx(u);
        RE[p] = xr[(3070 - u) & (N_CONV - 1)];   // (1022-u) mod 1024
        RO[p] = xr[(3071 - u) & (N_CONV - 1)];   // (1023-u) mod 1024
    }
    for (int u = tid; u < N_CONV; u += THREADS)
        X[u] = xr[u];
    __syncthreads();

    const int jh  = tid >> 7;          // j-quarter: j in [256*jh, 256*jh+256)
    const int wg  = tid & 127;
    const int par = wg >> 6;           // 0: even outputs, 1: odd outputs
    const int m   = wg & 63;
    const int k0e = m << 4;            // outputs k0e+par+2t, t=0..7
    const float* Rbase = par ? RO : RE;

    // Window block for it=0 at j0=256*jh: (63 - m) + 16*jh; +1 block per iter.
    const float* wp = Rbase + (63 - m + 16 * jh) * 20;

    u64t acc[8];
    #pragma unroll
    for (int t = 0; t < 8; ++t) acc[t] = 0ull;

    // Rolling window: wlo = logical floats B..B+15, whi = B+16..B+31.
    u64t wlo[8], whi[8];
    load8u64(wlo, wp); wp += 20;
    load8u64(whi, wp); wp += 20;

    const float* bp = X + 256 * jh;

    #pragma unroll 2
    for (int it = 0; it < ITERS; ++it) {
        // Broadcast pairs xp[q] = (x[j0+2q], x[j0+2q+1]).
        u64t xp[8];
        load8u64(xp, bp);
        bp += 16;

        // acc[t] lanes += (x[j], x[j+1]) * (x[k_t-j], x[k_t-j-1]);
        // window u64 index i = 7 - t + q, compile-time.
        #pragma unroll
        for (int q = 0; q < 8; ++q) {
            #pragma unroll
            for (int t = 0; t < 8; ++t) {
                const int i = 7 - t + q;
                const u64t w = (i < 8) ? wlo[i] : whi[i - 8];
                acc[t] = ffma2(xp[q], w, acc[t]);
            }
        }

        // Roll window down 16 logical floats; load next block.
        #pragma unroll
        for (int i = 0; i < 8; ++i) wlo[i] = whi[i];
        load8u64(whi, wp);
        wp += 20;
    }

    // Horizontal add lanes -> per-thread partials a[t].
    float a[8];
    #pragma unroll
    for (int t = 0; t < 8; ++t) {
        float lo, hi;
        unpack2(acc[t], lo, hi);
        a[t] = lo + hi;
    }

    // Combine the 4 j-quarters. jh>0 write partials to smem; jh==0 sums.
    if (jh > 0) {
        float* sp = &SP[(jh - 1) * N_CONV];
        #pragma unroll
        for (int t = 0; t < 8; ++t)
            sp[k0e + par + 2 * t] = a[t];
    }
    __syncthreads();

    if (jh == 0) {
        float* orow = out + (size_t)arr * 128 * N_CONV + (size_t)row * N_CONV;
        #pragma unroll
        for (int t = 0; t < 8; ++t) {
            const int k = k0e + par + 2 * t;
            orow[k] = a[t] + SP[k] + SP[N_CONV + k] + SP[2 * N_CONV + k];
        }
    }
}

extern "C" void kernel_launch(void* const* d_in, const int* in_sizes, int n_in,
                              void* d_out, int out_size)
{
    const float* x1 = (const float*)d_in[0];
    const float* x2 = (const float*)d_in[1];
    const float* x3 = (const float*)d_in[2];
    float* out = (float*)d_out;

    mcf_conv_kernel<<<384, THREADS>>>(x1, x2, x3, out);
}

// round 6
// speedup vs baseline: 2.2684x; 2.2684x over previous
#include <cuda_runtime.h>
#include <cuda_bf16.h>

// Circular self-convolution via FFT: out = IFFT( FFT(x)^2 ), N = 1024.
// B=128 rows x 3 arrays -> 384 independent transforms, one CTA (256 thr) each.
//
// Radix-4 in-place DIF forward (L = 1024,256,64,16,4): natural-order input,
// digit-reversed output. Pointwise square is done in the permuted basis
// (pointwise ops commute with permutations). The inverse runs the exact
// stage-by-stage inversion of the forward network (un-twiddle then inverse
// butterfly, L = 4,16,64,256,1024), so FFT->IFFT is identity by construction
// and no bit-reversal pass is needed. The 1/4-per-stage factors are folded
// into a single 1/1024 at the final store.
//
// The middle (fwd L=4 -> square -> inv L=4) is fused in registers (q=1 =>
// each thread owns its 4 points). The final inverse stage writes directly
// to gmem in natural order (coalesced).
//
// Twiddles: W^k = exp(-2*pi*i*k/1024) built once per CTA with sincospif
// (accurate); table in smem. Work: ~45 MFLOP total vs 804 MFLOP direct.

#define N_CONV 1024
#define THREADS 256

// Padded smem index: +1 float per 32 to break stride conflicts.
#define P(i) ((i) + ((i) >> 5))

template<int L>
__device__ __forceinline__ void fwd_stage(float* Xr, float* Xi,
                                          const float* Wr, const float* Wi,
                                          int t)
{
    const int q   = L >> 2;
    const int tws = N_CONV / L;
    const int blk  = t / q;
    const int pos  = t - blk * q;
    const int base = blk * L + pos;

    float a0r = Xr[P(base)],       a0i = Xi[P(base)];
    float a1r = Xr[P(base + q)],   a1i = Xi[P(base + q)];
    float a2r = Xr[P(base + 2*q)], a2i = Xi[P(base + 2*q)];
    float a3r = Xr[P(base + 3*q)], a3i = Xi[P(base + 3*q)];

    float t0r = a0r + a2r, t0i = a0i + a2i;
    float t1r = a0r - a2r, t1i = a0i - a2i;
    float t2r = a1r + a3r, t2i = a1i + a3i;
    float t3r = a1r - a3r, t3i = a1i - a3i;

    float o0r = t0r + t2r, o0i = t0i + t2i;
    float o2r = t0r - t2r, o2i = t0i - t2i;
    float o1r = t1r + t3i, o1i = t1i - t3r;   // t1 - i*t3
    float o3r = t1r - t3i, o3i = t1i + t3r;   // t1 + i*t3

    // Twiddle outputs 1..3 by W^(s*pos*tws)  (W = c + i*d, d = -sin)
    {
        const int w1 = pos * tws;
        float c, d, r;
        c = Wr[w1];     d = Wi[w1];     r = o1r;
        o1r = r*c - o1i*d;  o1i = r*d + o1i*c;
        c = Wr[2*w1];   d = Wi[2*w1];   r = o2r;
        o2r = r*c - o2i*d;  o2i = r*d + o2i*c;
        c = Wr[3*w1];   d = Wi[3*w1];   r = o3r;
        o3r = r*c - o3i*d;  o3i = r*d + o3i*c;
    }

    Xr[P(base)]       = o0r;  Xi[P(base)]       = o0i;
    Xr[P(base + q)]   = o1r;  Xi[P(base + q)]   = o1i;
    Xr[P(base + 2*q)] = o2r;  Xi[P(base + 2*q)] = o2i;
    Xr[P(base + 3*q)] = o3r;  Xi[P(base + 3*q)] = o3i;
}

template<int L>
__device__ __forceinline__ void inv_stage(float* Xr, float* Xi,
                                          const float* Wr, const float* Wi,
                                          int t)
{
    const int q   = L >> 2;
    const int tws = N_CONV / L;
    const int blk  = t / q;
    const int pos  = t - blk * q;
    const int base = blk * L + pos;

    float a0r = Xr[P(base)],       a0i = Xi[P(base)];
    float a1r = Xr[P(base + q)],   a1i = Xi[P(base + q)];
    float a2r = Xr[P(base + 2*q)], a2i = Xi[P(base + 2*q)];
    float a3r = Xr[P(base + 3*q)], a3i = Xi[P(base + 3*q)];

    // Un-twiddle: multiply by conj(W^(s*pos*tws)) = (c, -d)
    {
        const int w1 = pos * tws;
        float c, d, r;
        c = Wr[w1];     d = Wi[w1];     r = a1r;
        a1r = r*c + a1i*d;  a1i = a1i*c - r*d;
        c = Wr[2*w1];   d = Wi[2*w1];   r = a2r;
        a2r = r*c + a2i*d;  a2i = a2i*c - r*d;
        c = Wr[3*w1];   d = Wi[3*w1];   r = a3r;
        a3r = r*c + a3i*d;  a3i = a3i*c - r*d;
    }

    float t0r = a0r + a2r, t0i = a0i + a2i;
    float t1r = a0r - a2r, t1i = a0i - a2i;
    float t2r = a1r + a3r, t2i = a1i + a3i;
    float t3r = a1r - a3r, t3i = a1i - a3i;

    // Inverse butterfly (+i convention); 1/4 factor folded out.
    Xr[P(base)]       = t0r + t2r;  Xi[P(base)]       = t0i + t2i;
    Xr[P(base + 2*q)] = t0r - t2r;  Xi[P(base + 2*q)] = t0i - t2i;
    Xr[P(base + q)]   = t1r - t3i;  Xi[P(base + q)]   = t1i + t3r;  // t1 + i*t3
    Xr[P(base + 3*q)] = t1r + t3i;  Xi[P(base + 3*q)] = t1i - t3r;  // t1 - i*t3
}

__global__ __launch_bounds__(THREADS, 4)
void mcf_fft_kernel(const float* __restrict__ x1,
                    const float* __restrict__ x2,
                    const float* __restrict__ x3,
                    float* __restrict__ out)
{
    __shared__ __align__(16) float Xr[1056];
    __shared__ __align__(16) float Xi[1056];
    __shared__ __align__(16) float Wr[1024];
    __shared__ __align__(16) float Wi[1024];

    const int bx  = blockIdx.x;
    const int arr = bx >> 7;
    const int row = bx & 127;

    const float* x  = (arr == 0) ? x1 : ((arr == 1) ? x2 : x3);
    const float* xr = x + (size_t)row * N_CONV;

    const int t = threadIdx.x;

    // Twiddle table W^k = exp(-2*pi*i*k/1024), and input load (imag = 0).
    #pragma unroll
    for (int m = 0; m < 4; ++m) {
        const int k = t + 256 * m;
        float s, c;
        sincospif((float)k * (1.0f / 512.0f), &s, &c);
        Wr[k] = c;
        Wi[k] = -s;
        Xr[P(k)] = xr[k];
        Xi[P(k)] = 0.0f;
    }
    __syncthreads();

    // Forward DIF stages (through smem).
    fwd_stage<1024>(Xr, Xi, Wr, Wi, t); __syncthreads();
    fwd_stage< 256>(Xr, Xi, Wr, Wi, t); __syncthreads();
    fwd_stage<  64>(Xr, Xi, Wr, Wi, t); __syncthreads();
    fwd_stage<  16>(Xr, Xi, Wr, Wi, t); __syncthreads();

    // Fused: fwd L=4 (pos=0, twiddles = 1) -> square -> inv L=4, in registers.
    {
        const int base = 4 * t;
        float a0r = Xr[P(base)],   a0i = Xi[P(base)];
        float a1r = Xr[P(base+1)], a1i = Xi[P(base+1)];
        float a2r = Xr[P(base+2)], a2i = Xi[P(base+2)];
        float a3r = Xr[P(base+3)], a3i = Xi[P(base+3)];

        float t0r = a0r + a2r, t0i = a0i + a2i;
        float t1r = a0r - a2r, t1i = a0i - a2i;
        float t2r = a1r + a3r, t2i = a1i + a3i;
        float t3r = a1r - a3r, t3i = a1i - a3i;

        float y0r = t0r + t2r, y0i = t0i + t2i;
        float y2r = t0r - t2r, y2i = t0i - t2i;
        float y1r = t1r + t3i, y1i = t1i - t3r;
        float y3r = t1r - t3i, y3i = t1i + t3r;

        // Pointwise square: (r + i*im)^2
        float r;
        r = y0r; y0r = r*r - y0i*y0i; y0i = 2.0f*r*y0i;
        r = y1r; y1r = r*r - y1i*y1i; y1i = 2.0f*r*y1i;
        r = y2r; y2r = r*r - y2i*y2i; y2i = 2.0f*r*y2i;
        r = y3r; y3r = r*r - y3i*y3i; y3i = 2.0f*r*y3i;

        // Inverse L=4 butterfly (no twiddles).
        float u0r = y0r + y2r, u0i = y0i + y2i;
        float u1r = y0r - y2r, u1i = y0i - y2i;
        float u2r = y1r + y3r, u2i = y1i + y3i;
        float u3r = y1r - y3r, u3i = y1i - y3i;

        __syncthreads();
        Xr[P(base)]   = u0r + u2r;  Xi[P(base)]   = u0i + u2i;
        Xr[P(base+2)] = u0r - u2r;  Xi[P(base+2)] = u0i - u2i;
        Xr[P(base+1)] = u1r - u3i;  Xi[P(base+1)] = u1i + u3r;
        Xr[P(base+3)] = u1r + u3i;  Xi[P(base+3)] = u1i - u3r;
    }
    __syncthreads();

    // Inverse stages (undo in reverse order).
    inv_stage<  16>(Xr, Xi, Wr, Wi, t); __syncthreads();
    inv_stage<  64>(Xr, Xi, Wr, Wi, t); __syncthreads();
    inv_stage< 256>(Xr, Xi, Wr, Wi, t); __syncthreads();

    // Final inverse stage L=1024: q=256, blk=0, pos=t. Write gmem directly.
    {
        const int base = t;
        float a0r = Xr[P(base)],       a0i = Xi[P(base)];
        float a1r = Xr[P(base + 256)], a1i = Xi[P(base + 256)];
        float a2r = Xr[P(base + 512)], a2i = Xi[P(base + 512)];
        float a3r = Xr[P(base + 768)], a3i = Xi[P(base + 768)];

        float c, d, r;
        c = Wr[t];     d = Wi[t];     r = a1r;
        a1r = r*c + a1i*d;  a1i = a1i*c - r*d;
        c = Wr[2*t];   d = Wi[2*t];   r = a2r;
        a2r = r*c + a2i*d;  a2i = a2i*c - r*d;
        c = Wr[3*t];   d = Wi[3*t];   r = a3r;
        a3r = r*c + a3i*d;  a3i = a3i*c - r*d;

        float t0r = a0r + a2r;
        float t1r = a0r - a2r;
        float t2r = a1r + a3r;
        float t3i = a1i - a3i;

        const float inv_n = 1.0f / 1024.0f;
        float* orow = out + (size_t)arr * 128 * N_CONV + (size_t)row * N_CONV;
        orow[t]       = (t0r + t2r) * inv_n;
        orow[t + 512] = (t0r - t2r) * inv_n;
        orow[t + 256] = (t1r - t3i) * inv_n;
        orow[t + 768] = (t1r + t3i) * inv_n;
    }
}

extern "C" void kernel_launch(void* const* d_in, const int* in_sizes, int n_in,
                              void* d_out, int out_size)
{
    const float* x1 = (const float*)d_in[0];
    const float* x2 = (const float*)d_in[1];
    const float* x3 = (const float*)d_in[2];
    float* out = (float*)d_out;

    mcf_fft_kernel<<<384, THREADS>>>(x1, x2, x3, out);
}

// round 7
// speedup vs baseline: 2.7485x; 1.2117x over previous
#include <cuda_runtime.h>
#include <cuda_bf16.h>

// Circular self-convolution via packed real FFT: two real rows per complex
// transform. z = xa + i*xb; FFT(z); unpack by conjugate symmetry; square
// both spectra; repack Y = Ya + i*Yb; IFFT(Y) -> re = conv_a, im = conv_b.
// 384 rows -> 192 CTAs (256 threads each), ~2x fewer instructions than R6.
//
// Radix-4 in-place DIF forward (L=1024..4): natural input, digit-reversed
// output (position p holds X[rev4(p)], rev4 = base-4 digit reversal of the
// 5-digit index == bit-pair reversal of the 10-bit index; verified).
// Mirror index for conj symmetry: pm = rev4((1024 - rev4(p)) mod 1024).
// Inverse = exact stage-by-stage inversion (L=4..1024), so no reorder pass;
// 1/1024 folded into the final store.

#define N_CONV 1024
#define THREADS 256

// Padded smem index: +1 float per 32 to break stride conflicts.
#define P(i) ((i) + ((i) >> 5))

__device__ __forceinline__ int rev4(int p) {
    return ((p & 3) << 8) | (((p >> 2) & 3) << 6) | (((p >> 4) & 3) << 4)
         | (((p >> 6) & 3) << 2) | ((p >> 8) & 3);
}

template<int L>
__device__ __forceinline__ void fwd_stage(float* Xr, float* Xi,
                                          const float* Wr, const float* Wi,
                                          int t)
{
    const int q   = L >> 2;
    const int tws = N_CONV / L;
    const int blk  = t / q;
    const int pos  = t - blk * q;
    const int base = blk * L + pos;

    float a0r = Xr[P(base)],       a0i = Xi[P(base)];
    float a1r = Xr[P(base + q)],   a1i = Xi[P(base + q)];
    float a2r = Xr[P(base + 2*q)], a2i = Xi[P(base + 2*q)];
    float a3r = Xr[P(base + 3*q)], a3i = Xi[P(base + 3*q)];

    float t0r = a0r + a2r, t0i = a0i + a2i;
    float t1r = a0r - a2r, t1i = a0i - a2i;
    float t2r = a1r + a3r, t2i = a1i + a3i;
    float t3r = a1r - a3r, t3i = a1i - a3i;

    float o0r = t0r + t2r, o0i = t0i + t2i;
    float o2r = t0r - t2r, o2i = t0i - t2i;
    float o1r = t1r + t3i, o1i = t1i - t3r;   // t1 - i*t3
    float o3r = t1r - t3i, o3i = t1i + t3r;   // t1 + i*t3

    {
        const int w1 = pos * tws;
        float c, d, r;
        c = Wr[w1];     d = Wi[w1];     r = o1r;
        o1r = r*c - o1i*d;  o1i = r*d + o1i*c;
        c = Wr[2*w1];   d = Wi[2*w1];   r = o2r;
        o2r = r*c - o2i*d;  o2i = r*d + o2i*c;
        c = Wr[3*w1];   d = Wi[3*w1];   r = o3r;
        o3r = r*c - o3i*d;  o3i = r*d + o3i*c;
    }

    Xr[P(base)]       = o0r;  Xi[P(base)]       = o0i;
    Xr[P(base + q)]   = o1r;  Xi[P(base + q)]   = o1i;
    Xr[P(base + 2*q)] = o2r;  Xi[P(base + 2*q)] = o2i;
    Xr[P(base + 3*q)] = o3r;  Xi[P(base + 3*q)] = o3i;
}

template<int L>
__device__ __forceinline__ void inv_stage(float* Xr, float* Xi,
                                          const float* Wr, const float* Wi,
                                          int t)
{
    const int q   = L >> 2;
    const int tws = N_CONV / L;
    const int blk  = t / q;
    const int pos  = t - blk * q;
    const int base = blk * L + pos;

    float a0r = Xr[P(base)],       a0i = Xi[P(base)];
    float a1r = Xr[P(base + q)],   a1i = Xi[P(base + q)];
    float a2r = Xr[P(base + 2*q)], a2i = Xi[P(base + 2*q)];
    float a3r = Xr[P(base + 3*q)], a3i = Xi[P(base + 3*q)];

    // Un-twiddle by conj(W^..) = (c, -d)
    {
        const int w1 = pos * tws;
        float c, d, r;
        c = Wr[w1];     d = Wi[w1];     r = a1r;
        a1r = r*c + a1i*d;  a1i = a1i*c - r*d;
        c = Wr[2*w1];   d = Wi[2*w1];   r = a2r;
        a2r = r*c + a2i*d;  a2i = a2i*c - r*d;
        c = Wr[3*w1];   d = Wi[3*w1];   r = a3r;
        a3r = r*c + a3i*d;  a3i = a3i*c - r*d;
    }

    float t0r = a0r + a2r, t0i = a0i + a2i;
    float t1r = a0r - a2r, t1i = a0i - a2i;
    float t2r = a1r + a3r, t2i = a1i + a3i;
    float t3r = a1r - a3r, t3i = a1i - a3i;

    // Inverse butterfly (+i convention); 1/4 folded out.
    Xr[P(base)]       = t0r + t2r;  Xi[P(base)]       = t0i + t2i;
    Xr[P(base + 2*q)] = t0r - t2r;  Xi[P(base + 2*q)] = t0i - t2i;
    Xr[P(base + q)]   = t1r - t3i;  Xi[P(base + q)]   = t1i + t3r;  // t1 + i*t3
    Xr[P(base + 3*q)] = t1r + t3i;  Xi[P(base + 3*q)] = t1i - t3r;  // t1 - i*t3
}

__global__ __launch_bounds__(THREADS, 2)
void mcf_fft2_kernel(const float* __restrict__ x1,
                     const float* __restrict__ x2,
                     const float* __restrict__ x3,
                     float* __restrict__ out)
{
    __shared__ __align__(16) float Xr[1056];
    __shared__ __align__(16) float Xi[1056];
    __shared__ __align__(16) float Wr[1024];
    __shared__ __align__(16) float Wi[1024];

    const int bx = blockIdx.x;             // 0..191: row pair
    const int rA = 2 * bx;                 // global rows rA, rA+1 (same array)
    const int arr = rA >> 7;
    const int lA  = rA & 127;

    const float* x  = (arr == 0) ? x1 : ((arr == 1) ? x2 : x3);
    const float* xa = x + (size_t)lA * N_CONV;
    const float* xb = xa + N_CONV;

    const int t = threadIdx.x;

    // Twiddles W^k = exp(-2*pi*i*k/1024); packed input z = xa + i*xb.
    #pragma unroll
    for (int m = 0; m < 4; ++m) {
        const int k = t + 256 * m;
        float s, c;
        sincospif((float)k * (1.0f / 512.0f), &s, &c);
        Wr[k] = c;
        Wi[k] = -s;
        Xr[P(k)] = xa[k];
        Xi[P(k)] = xb[k];
    }
    __syncthreads();

    // Forward DIF stages.
    fwd_stage<1024>(Xr, Xi, Wr, Wi, t); __syncthreads();
    fwd_stage< 256>(Xr, Xi, Wr, Wi, t); __syncthreads();
    fwd_stage<  64>(Xr, Xi, Wr, Wi, t); __syncthreads();
    fwd_stage<  16>(Xr, Xi, Wr, Wi, t); __syncthreads();
    fwd_stage<   4>(Xr, Xi, Wr, Wi, t); __syncthreads();

    // Middle: unpack conj-symmetric pair, square both spectra, repack.
    // Position p holds Z[rev4(p)]; mirror pm = rev4((1024 - k) & 1023).
    {
        float yr[4], yi[4];
        #pragma unroll
        for (int m = 0; m < 4; ++m) {
            const int p  = t + 256 * m;
            const int k  = rev4(p);
            const int pm = rev4((N_CONV - k) & (N_CONV - 1));

            const float Zr = Xr[P(p)],  Zi = Xi[P(p)];
            const float Mr = Xr[P(pm)], Mi = Xi[P(pm)];

            // Xa = (Z + conj(M))/2 ; Xb = (Z - conj(M))/(2i)
            const float Ar = 0.5f * (Zr + Mr), Ai = 0.5f * (Zi - Mi);
            const float Br = 0.5f * (Zi + Mi), Bi = 0.5f * (Mr - Zr);

            // Squares, then Y = Ya + i*Yb.
            const float Yar = Ar*Ar - Ai*Ai, Yai = 2.0f*Ar*Ai;
            const float Ybr = Br*Br - Bi*Bi, Ybi = 2.0f*Br*Bi;
            yr[m] = Yar - Ybi;
            yi[m] = Yai + Ybr;
        }
        __syncthreads();   // all mirror reads done before in-place writes
        #pragma unroll
        for (int m = 0; m < 4; ++m) {
            const int p = t + 256 * m;
            Xr[P(p)] = yr[m];
            Xi[P(p)] = yi[m];
        }
    }
    __syncthreads();

    // Inverse stages (undo forward in reverse order).
    inv_stage<   4>(Xr, Xi, Wr, Wi, t); __syncthreads();
    inv_stage<  16>(Xr, Xi, Wr, Wi, t); __syncthreads();
    inv_stage<  64>(Xr, Xi, Wr, Wi, t); __syncthreads();
    inv_stage< 256>(Xr, Xi, Wr, Wi, t); __syncthreads();

    // Final inverse stage L=1024 (q=256, pos=t): write both rows to gmem.
    {
        float a0r = Xr[P(t)],       a0i = Xi[P(t)];
        float a1r = Xr[P(t + 256)], a1i = Xi[P(t + 256)];
        float a2r = Xr[P(t + 512)], a2i = Xi[P(t + 512)];
        float a3r = Xr[P(t + 768)], a3i = Xi[P(t + 768)];

        float c, d, r;
        c = Wr[t];     d = Wi[t];     r = a1r;
        a1r = r*c + a1i*d;  a1i = a1i*c - r*d;
        c = Wr[2*t];   d = Wi[2*t];   r = a2r;
        a2r = r*c + a2i*d;  a2i = a2i*c - r*d;
        c = Wr[3*t];   d = Wi[3*t];   r = a3r;
        a3r = r*c + a3i*d;  a3i = a3i*c - r*d;

        float t0r = a0r + a2r, t0i = a0i + a2i;
        float t1r = a0r - a2r, t1i = a0i - a2i;
        float t2r = a1r + a3r, t2i = a1i + a3i;
        float t3r = a1r - a3r, t3i = a1i - a3i;

        const float inv_n = 1.0f / 1024.0f;
        float* orowA = out + (size_t)arr * 128 * N_CONV + (size_t)lA * N_CONV;
        float* orowB = orowA + N_CONV;

        // n = t        : t0 + t2
        orowA[t]       = (t0r + t2r) * inv_n;
        orowB[t]       = (t0i + t2i) * inv_n;
        // n = t + 512  : t0 - t2
        orowA[t + 512] = (t0r - t2r) * inv_n;
        orowB[t + 512] = (t0i - t2i) * inv_n;
        // n = t + 256  : t1 + i*t3
        orowA[t + 256] = (t1r - t3i) * inv_n;
        orowB[t + 256] = (t1i + t3r) * inv_n;
        // n = t + 768  : t1 - i*t3
        orowA[t + 768] = (t1r + t3i) * inv_n;
        orowB[t + 768] = (t1i - t3r) * inv_n;
    }
}

extern "C" void kernel_launch(void* const* d_in, const int* in_sizes, int n_in,
                              void* d_out, int out_size)
{
    const float* x1 = (const float*)d_in[0];
    const float* x2 = (const float*)d_in[1];
    const float* x3 = (const float*)d_in[2];
    float* out = (float*)d_out;

    mcf_fft2_kernel<<<192, THREADS>>>(x1, x2, x3, out);
}